// round 6
// baseline (speedup 1.0000x reference)
#include <cuda_runtime.h>

// Problem constants: B=2048, F=40, E=64, I=780
#define FDIM   40
#define EDIM   64
#define NPAIR  780
#define NGR    10            // field groups of 4
#define NFULL  45            // C(10,2) full 4x4 tiles
#define NTILE  55            // + 10 diagonal (intra-group) tiles
#define BT     32            // batches per block (= warp lanes)
#define PH_E2  16            // float2 e-chunks staged per phase (32 e)
#define SLOTS  16            // 2 block-halves x 8 warps

__device__ float g_ksum[NPAIR * EDIM];

// ---------------------------------------------------------------------------
// Kernel 1: ksum[p][e] = sum_k kernel[k][p][e]
// ---------------------------------------------------------------------------
__global__ void ksum_kernel(const float* __restrict__ kern)
{
    const int n4 = NPAIR * EDIM / 4;
    int idx4 = blockIdx.x * blockDim.x + threadIdx.x;
    if (idx4 >= n4) return;
    const float4* k4 = reinterpret_cast<const float4*>(kern);
    float4 s = make_float4(0.f, 0.f, 0.f, 0.f);
    #pragma unroll 8
    for (int k = 0; k < EDIM; ++k) {
        float4 v = k4[(size_t)k * n4 + idx4];
        s.x += v.x; s.y += v.y; s.z += v.z; s.w += v.w;
    }
    reinterpret_cast<float4*>(g_ksum)[idx4] = s;
}

// ---------------------------------------------------------------------------
// f32x2 packed-math helpers (FFMA2 path; only reachable via PTX)
// ---------------------------------------------------------------------------
__device__ __forceinline__ unsigned long long mul2(unsigned long long ua,
                                                   unsigned long long ub)
{
    unsigned long long ur;
    asm("mul.rn.f32x2 %0, %1, %2;" : "=l"(ur) : "l"(ua), "l"(ub));
    return ur;
}
__device__ __forceinline__ unsigned long long fma2(unsigned long long ua,
                                                   unsigned long long ub,
                                                   unsigned long long uc)
{
    unsigned long long ur;
    asm("fma.rn.f32x2 %0, %1, %2, %3;" : "=l"(ur) : "l"(ua), "l"(ub), "l"(uc));
    return ur;
}
__device__ __forceinline__ float sum2(unsigned long long ua)
{
    float lo, hi;
    asm("mov.b64 {%0, %1}, %2;" : "=f"(lo), "=f"(hi) : "l"(ua));
    return lo + hi;
}
__device__ __forceinline__ unsigned long long packf2(float a, float b)
{
    unsigned long long u;
    asm("mov.b64 %0, {%1, %2};" : "=l"(u) : "f"(a), "f"(b));
    return u;
}

__device__ __forceinline__ int pair_off(int i) { return i * 39 - (i * (i - 1)) / 2; }

// ---------------------------------------------------------------------------
// Kernel 2. Layout: smem sm2[(f*16 + el)*32 + (b ^ swz)] holds float2
// (e = 32*ph + 2*el .. +1) of batch b, swz = (9*(el>>1)) & 31.
// Lane = batch -> every LDS/STS is a contiguous 256B run: conflict-free.
// ---------------------------------------------------------------------------
__global__ void __launch_bounds__(256, 1) interact_kernel(
    const float* __restrict__ A,    // (B, 40, 64)
    float*       __restrict__ out)  // (B, 780)
{
    extern __shared__ unsigned long long sm2[];

    const int tid  = threadIdx.x;
    const int lane = tid & 31;
    const int warp = tid >> 5;
    const int bgroup = blockIdx.x >> 1;
    const int half   = blockIdx.x & 1;
    const int slot   = half * 8 + warp;
    const int b0     = bgroup * BT;
    float* orow = out + (size_t)(b0 + lane) * NPAIR;

    const float4* A4 = reinterpret_cast<const float4*>(A);
    const ulonglong2* w2 = reinterpret_cast<const ulonglong2*>(g_ksum);

    for (int ph = 0; ph < 2; ++ph) {
        if (ph) __syncthreads();   // finish phase-0 compute before restage

        // ---- stage 32 batches x 40 fields x 32 e (this phase) ----
        #pragma unroll 4
        for (int it = 0; it < 40; ++it) {
            int v  = it * 256 + tid;
            int e4 = v & 7;              // float4 within phase (coalesced)
            int b  = (v >> 3) & 31;
            int f  = v >> 8;
            float4 val = A4[(size_t)(b0 + b) * (FDIM * 16) + f * 16 + ph * 8 + e4];
            int swz = (9 * e4) & 31;
            int d = (f * PH_E2 + 2 * e4) * 32 + (b ^ swz);
            sm2[d]      = packf2(val.x, val.y);
            sm2[d + 32] = packf2(val.z, val.w);
        }
        __syncthreads();

        // ---- compute this slot's tiles ----
        for (int t = slot; t < NTILE; t += SLOTS) {
            if (t < NFULL) {
                // full 4x4 tile between groups gi < gj
                int gi = 0, cum = 0;
                while (cum + (NGR - 1 - gi) <= t) { cum += NGR - 1 - gi; ++gi; }
                int gj = gi + 1 + (t - cum);
                const int i0 = 4 * gi, j0 = 4 * gj;

                int pb[4];
                #pragma unroll
                for (int a = 0; a < 4; ++a)
                    pb[a] = pair_off(i0 + a) + (j0 - (i0 + a) - 1);

                unsigned long long acc[16];
                #pragma unroll
                for (int q = 0; q < 16; ++q) acc[q] = 0ull;

                for (int s = 0; s < 8; ++s) {       // 4 e per step
                    const int pos = lane ^ ((9 * s) & 31);
                    unsigned long long xi[4][2], xj[4][2];
                    #pragma unroll
                    for (int r = 0; r < 4; ++r) {
                        int di = ((i0 + r) * PH_E2 + 2 * s) * 32 + pos;
                        int dj = ((j0 + r) * PH_E2 + 2 * s) * 32 + pos;
                        xi[r][0] = sm2[di]; xi[r][1] = sm2[di + 32];
                        xj[r][0] = sm2[dj]; xj[r][1] = sm2[dj + 32];
                    }
                    const int widx = 8 * ph + s;     // float4 index within w row
                    #pragma unroll
                    for (int a = 0; a < 4; ++a) {
                        #pragma unroll
                        for (int bb = 0; bb < 4; ++bb) {
                            // 16B NC load: two packed f32x2 of w
                            ulonglong2 wv = __ldg(&w2[(size_t)(pb[a] + bb) * 16 + widx]);
                            const int q = a * 4 + bb;
                            acc[q] = fma2(mul2(xi[a][0], xj[bb][0]), wv.x, acc[q]);
                            acc[q] = fma2(mul2(xi[a][1], xj[bb][1]), wv.y, acc[q]);
                        }
                    }
                }

                #pragma unroll
                for (int a = 0; a < 4; ++a)
                    #pragma unroll
                    for (int bb = 0; bb < 4; ++bb) {
                        float r_ = sum2(acc[a * 4 + bb]);
                        float* po = orow + pb[a] + bb;
                        if (ph) r_ += *po;
                        *po = r_;
                    }
            } else {
                // diagonal tile: group g, 6 intra-group pairs
                const int g  = t - NFULL;
                const int i0 = 4 * g;
                const int pa[6] = {0, 0, 0, 1, 1, 2};
                const int pbb[6] = {1, 2, 3, 2, 3, 3};
                int pidx[6];
                #pragma unroll
                for (int q = 0; q < 6; ++q)
                    pidx[q] = pair_off(i0 + pa[q]) + (pbb[q] - pa[q] - 1);

                unsigned long long acc[6];
                #pragma unroll
                for (int q = 0; q < 6; ++q) acc[q] = 0ull;

                for (int s = 0; s < 8; ++s) {
                    const int pos = lane ^ ((9 * s) & 31);
                    unsigned long long x[4][2];
                    #pragma unroll
                    for (int r = 0; r < 4; ++r) {
                        int d = ((i0 + r) * PH_E2 + 2 * s) * 32 + pos;
                        x[r][0] = sm2[d]; x[r][1] = sm2[d + 32];
                    }
                    const int widx = 8 * ph + s;
                    #pragma unroll
                    for (int q = 0; q < 6; ++q) {
                        ulonglong2 wv = __ldg(&w2[(size_t)pidx[q] * 16 + widx]);
                        acc[q] = fma2(mul2(x[pa[q]][0], x[pbb[q]][0]), wv.x, acc[q]);
                        acc[q] = fma2(mul2(x[pa[q]][1], x[pbb[q]][1]), wv.y, acc[q]);
                    }
                }

                #pragma unroll
                for (int q = 0; q < 6; ++q) {
                    float r_ = sum2(acc[q]);
                    float* po = orow + pidx[q];
                    if (ph) r_ += *po;
                    *po = r_;
                }
            }
        }
    }
}

// ---------------------------------------------------------------------------
// Launch
// ---------------------------------------------------------------------------
extern "C" void kernel_launch(void* const* d_in, const int* in_sizes, int n_in,
                              void* d_out, int out_size)
{
    const float* inputs = (const float*)d_in[0];
    const float* kern   = (const float*)d_in[1];
    (void)n_in; (void)out_size;

    const int B = in_sizes[0] / (FDIM * EDIM);     // 2048
    const size_t smem_bytes = (size_t)FDIM * PH_E2 * 32 * sizeof(unsigned long long); // 163840

    cudaFuncSetAttribute(interact_kernel,
                         cudaFuncAttributeMaxDynamicSharedMemorySize,
                         (int)smem_bytes);

    {
        const int n4 = NPAIR * EDIM / 4;
        ksum_kernel<<<(n4 + 255) / 256, 256>>>(kern);
    }
    interact_kernel<<<(B / BT) * 2, 256, smem_bytes>>>(inputs, (float*)d_out);
}

// round 7
// speedup vs baseline: 1.6626x; 1.6626x over previous
#include <cuda_runtime.h>

// Problem constants: B=2048, F=40, E=64, I=780
#define FDIM   40
#define EDIM   64
#define NPAIR  780
#define NGR    10            // field groups of 4
#define NFULL  45            // C(10,2) full 4x4 tiles
#define NTILE  55            // + 10 diagonal (intra-group) tiles
#define BT     8             // batches per block; lane = 4*b + e_quarter
#define STEPS  4             // float4 e-chunks per lane (16 e per lane)

__device__ float g_ksum[NPAIR * EDIM];

// ---------------------------------------------------------------------------
// Kernel 1: ksum[p][e] = sum_k kernel[k][p][e]
// ---------------------------------------------------------------------------
__global__ void ksum_kernel(const float* __restrict__ kern)
{
    const int n4 = NPAIR * EDIM / 4;
    int idx4 = blockIdx.x * blockDim.x + threadIdx.x;
    if (idx4 >= n4) return;
    const float4* k4 = reinterpret_cast<const float4*>(kern);
    float4 s = make_float4(0.f, 0.f, 0.f, 0.f);
    #pragma unroll 8
    for (int k = 0; k < EDIM; ++k) {
        float4 v = k4[(size_t)k * n4 + idx4];
        s.x += v.x; s.y += v.y; s.z += v.z; s.w += v.w;
    }
    reinterpret_cast<float4*>(g_ksum)[idx4] = s;
}

// ---------------------------------------------------------------------------
// f32x2 packed-math helpers
// ---------------------------------------------------------------------------
__device__ __forceinline__ unsigned long long mul2(unsigned long long a,
                                                   unsigned long long b)
{
    unsigned long long r;
    asm("mul.rn.f32x2 %0, %1, %2;" : "=l"(r) : "l"(a), "l"(b));
    return r;
}
__device__ __forceinline__ unsigned long long fma2(unsigned long long a,
                                                   unsigned long long b,
                                                   unsigned long long c)
{
    unsigned long long r;
    asm("fma.rn.f32x2 %0, %1, %2, %3;" : "=l"(r) : "l"(a), "l"(b), "l"(c));
    return r;
}
__device__ __forceinline__ float sum2(unsigned long long a)
{
    float lo, hi;
    asm("mov.b64 {%0, %1}, %2;" : "=f"(lo), "=f"(hi) : "l"(a));
    return lo + hi;
}

__device__ __forceinline__ int pair_off(int i) { return i * 39 - (i * (i - 1)) / 2; }

// ---------------------------------------------------------------------------
// Kernel 2. smem: sm4[(f*4 + s)*32 + ((4b+q) ^ s)] = float4 of A[b0+b][f][e],
// e-chunk e4 = 4q+s. Lane l = 4b+q owns (batch b, e-quarter q).
// All LDS/STS hit the 4-wavefront floor (XOR is a per-row permutation).
// ---------------------------------------------------------------------------
__global__ void __launch_bounds__(256, 2) interact_kernel(
    const float* __restrict__ A,    // (B, 40, 64)
    float*       __restrict__ out)  // (B, 780)
{
    extern __shared__ ulonglong2 sm4[];   // 40*4*32 entries = 80 KB

    const int tid  = threadIdx.x;
    const int lane = tid & 31;
    const int warp = tid >> 5;
    const int b0   = blockIdx.x * BT;

    // ---- stage 8 batches x 40 fields x 64 e, once ----
    const float4* A4 = reinterpret_cast<const float4*>(A);
    #pragma unroll 5
    for (int it = 0; it < 20; ++it) {
        int v  = it * 256 + tid;
        int e4 = v & 15;
        int b  = (v >> 4) & 7;
        int f  = v >> 7;
        float4 val = A4[(size_t)(b0 + b) * (FDIM * 16) + f * 16 + e4];
        int s = e4 & 3, q = e4 >> 2;
        sm4[(f * 4 + s) * 32 + ((4 * b + q) ^ s)] =
            *reinterpret_cast<ulonglong2*>(&val);
    }
    __syncthreads();

    const ulonglong2* w4 = reinterpret_cast<const ulonglong2*>(g_ksum);
    const int q  = lane & 3;       // e-quarter
    const int bq = lane >> 2;      // batch within block
    float* orow = out + (size_t)(b0 + bq) * NPAIR;

    for (int t = warp; t < NTILE; t += 8) {
        if (t < NFULL) {
            // ---- full 4x4 tile between groups gi < gj ----
            int gi = 0, cum = 0;
            while (cum + (NGR - 1 - gi) <= t) { cum += NGR - 1 - gi; ++gi; }
            int gj = gi + 1 + (t - cum);
            const int i0 = 4 * gi, j0 = 4 * gj;

            int pb[4];
            #pragma unroll
            for (int a = 0; a < 4; ++a)
                pb[a] = pair_off(i0 + a) + (j0 - (i0 + a) - 1);

            unsigned long long acc[16];
            #pragma unroll
            for (int k = 0; k < 16; ++k) acc[k] = 0ull;

            #pragma unroll
            for (int s = 0; s < STEPS; ++s) {
                const int sl = lane ^ s;
                ulonglong2 xi[4], xj[4];
                #pragma unroll
                for (int r = 0; r < 4; ++r) {
                    xi[r] = sm4[((i0 + r) * 4 + s) * 32 + sl];
                    xj[r] = sm4[((j0 + r) * 4 + s) * 32 + sl];
                }
                const int we = 4 * q + s;          // e4 index for this lane
                #pragma unroll
                for (int a = 0; a < 4; ++a) {
                    #pragma unroll
                    for (int bb = 0; bb < 4; ++bb) {
                        ulonglong2 wv = __ldg(&w4[(size_t)(pb[a] + bb) * 16 + we]);
                        const int k = a * 4 + bb;
                        acc[k] = fma2(mul2(xi[a].x, xj[bb].x), wv.x, acc[k]);
                        acc[k] = fma2(mul2(xi[a].y, xj[bb].y), wv.y, acc[k]);
                    }
                }
            }

            #pragma unroll
            for (int a = 0; a < 4; ++a)
                #pragma unroll
                for (int bb = 0; bb < 4; ++bb) {
                    float r = sum2(acc[a * 4 + bb]);
                    r += __shfl_xor_sync(0xffffffffu, r, 2);
                    r += __shfl_xor_sync(0xffffffffu, r, 1);
                    if (q == 0) orow[pb[a] + bb] = r;
                }
        } else {
            // ---- diagonal tile: group g, 6 intra-group pairs ----
            const int g  = t - NFULL;
            const int i0 = 4 * g;
            const int pa[6]  = {0, 0, 0, 1, 1, 2};
            const int pc[6]  = {1, 2, 3, 2, 3, 3};
            int pidx[6];
            #pragma unroll
            for (int k = 0; k < 6; ++k)
                pidx[k] = pair_off(i0 + pa[k]) + (pc[k] - pa[k] - 1);

            unsigned long long acc[6];
            #pragma unroll
            for (int k = 0; k < 6; ++k) acc[k] = 0ull;

            #pragma unroll
            for (int s = 0; s < STEPS; ++s) {
                const int sl = lane ^ s;
                ulonglong2 x[4];
                #pragma unroll
                for (int r = 0; r < 4; ++r)
                    x[r] = sm4[((i0 + r) * 4 + s) * 32 + sl];
                const int we = 4 * q + s;
                #pragma unroll
                for (int k = 0; k < 6; ++k) {
                    ulonglong2 wv = __ldg(&w4[(size_t)pidx[k] * 16 + we]);
                    acc[k] = fma2(mul2(x[pa[k]].x, x[pc[k]].x), wv.x, acc[k]);
                    acc[k] = fma2(mul2(x[pa[k]].y, x[pc[k]].y), wv.y, acc[k]);
                }
            }

            #pragma unroll
            for (int k = 0; k < 6; ++k) {
                float r = sum2(acc[k]);
                r += __shfl_xor_sync(0xffffffffu, r, 2);
                r += __shfl_xor_sync(0xffffffffu, r, 1);
                if (q == 0) orow[pidx[k]] = r;
            }
        }
    }
}

// ---------------------------------------------------------------------------
// Launch
// ---------------------------------------------------------------------------
extern "C" void kernel_launch(void* const* d_in, const int* in_sizes, int n_in,
                              void* d_out, int out_size)
{
    const float* inputs = (const float*)d_in[0];
    const float* kern   = (const float*)d_in[1];
    (void)n_in; (void)out_size;

    const int B = in_sizes[0] / (FDIM * EDIM);              // 2048
    const size_t smem_bytes = (size_t)FDIM * 4 * 32 * 16;   // 81920 = 80 KB

    cudaFuncSetAttribute(interact_kernel,
                         cudaFuncAttributeMaxDynamicSharedMemorySize,
                         (int)smem_bytes);

    {
        const int n4 = NPAIR * EDIM / 4;
        ksum_kernel<<<(n4 + 255) / 256, 256>>>(kern);
    }
    interact_kernel<<<B / BT, 256, smem_bytes>>>(inputs, (float*)d_out);
}